// round 6
// baseline (speedup 1.0000x reference)
#include <cuda_runtime.h>
#include <math.h>

#define S    8
#define H    128
#define BB   4096
#define NBLK 128     // 32 batches (= 32 output rows) per block
#define NT   512

// Dynamic smem layout (floats)
#define OFF_WS   0            // Ws [128][128]          16384 floats
#define OFF_CS   16384        // Cs [32][128]            4096
#define OFF_RED  20480        // red (2048 u64)          4096
#define OFF_NS   24576        // ns [8][128]             1024
#define OFF_U1   25600        // u1s[128]
#define OFF_U2   25728        // u2s[128]
#define SMEM_FLOATS 25856
#define SMEM_BYTES  (SMEM_FLOATS * 4)

// ---- packed f32x2 helpers (ptxas never auto-fuses; PTX only) ----
__device__ __forceinline__ unsigned long long pk2(float lo, float hi) {
    unsigned long long r;
    asm("mov.b64 %0, {%1, %2};" : "=l"(r) : "f"(lo), "f"(hi));
    return r;
}
__device__ __forceinline__ void upk2(float& lo, float& hi, unsigned long long v) {
    asm("mov.b64 {%0, %1}, %2;" : "=f"(lo), "=f"(hi) : "l"(v));
}
__device__ __forceinline__ unsigned long long fma2(unsigned long long a,
                                                   unsigned long long b,
                                                   unsigned long long c) {
    unsigned long long d;
    asm("fma.rn.f32x2 %0, %1, %2, %3;" : "=l"(d) : "l"(a), "l"(b), "l"(c));
    return d;
}
__device__ __forceinline__ unsigned long long add2(unsigned long long a,
                                                   unsigned long long b) {
    unsigned long long d;
    asm("add.rn.f32x2 %0, %1, %2;" : "=l"(d) : "l"(a), "l"(b));
    return d;
}

__global__ __launch_bounds__(NT)
void fused_kernel(const float* __restrict__ memory,
                  const float* __restrict__ o_emb_w,
                  const float* __restrict__ o_emb_r,
                  const float* __restrict__ attn_W,
                  const float* __restrict__ sim_w,
                  const float* __restrict__ sim_b,
                  const float* __restrict__ forget_w,
                  const int*   __restrict__ o_rg_p,
                  const int*   __restrict__ d_rg,
                  float*       __restrict__ out)
{
    extern __shared__ float sm[];
    float* Ws  = sm + OFF_WS;
    float* Cs  = sm + OFF_CS;
    unsigned long long* redL = (unsigned long long*)(sm + OFF_RED);   // [4][256]
    unsigned long long* redH = redL + 1024;
    float* ns  = sm + OFF_NS;
    float* u1s = sm + OFF_U1;
    float* u2s = sm + OFF_U2;

    const int tid  = threadIdx.x;
    const int warp = tid >> 5;       // 0..15
    const int lane = tid & 31;
    const int orr  = o_rg_p[0];

    // ============ PHASE A: issue all independent memory ops early ============
    // 1) attend gather (latency hidden under the rest of phase A)
    const int bA = blockIdx.x * 32 + warp * 2;
    const int bB = bA + 1;
    const int rA = d_rg[bA];
    const int rB = d_rg[bB];
    float4 kmA[S], kmB[S];
    {
        const float4* sA = (const float4*)(memory + (size_t)rA * (S * H));
        const float4* sB = (const float4*)(memory + (size_t)rB * (S * H));
#pragma unroll
        for (int s = 0; s < S; s++) kmA[s] = sA[s * 32 + lane];
#pragma unroll
        for (int s = 0; s < S; s++) kmB[s] = sB[s * 32 + lane];
    }
    float4 oA = ((const float4*)(o_emb_r + (size_t)bA * H))[lane];
    float4 oB = ((const float4*)(o_emb_r + (size_t)bB * H))[lane];

    // 2) W -> smem, full 128x128 (4096 float4, 8 per thread)
    {
        const float4* W4  = (const float4*)attn_W;
        float4*       Ws4 = (float4*)Ws;
#pragma unroll
        for (int i = 0; i < 8; i++) Ws4[tid + i * NT] = W4[tid + i * NT];
    }

    // 3) gate + new_slot (warps 0..7, warp w = slot w, warp-local)
    if (warp < 8) {
        const float4* sel4 = (const float4*)(memory + (size_t)orr * (S * H) + warp * H);
        float4 v  = sel4[lane];
        float4 oe = ((const float4*)o_emb_w)[lane];
        float4 f1 = ((const float4*)forget_w)[lane];
        float4 f2 = ((const float4*)(forget_w + H))[lane];
        float d = oe.x*f1.x + oe.y*f1.y + oe.z*f1.z + oe.w*f1.w
                + v.x*f2.x  + v.y*f2.y  + v.z*f2.z  + v.w*f2.w;
#pragma unroll
        for (int off = 16; off > 0; off >>= 1)
            d += __shfl_xor_sync(0xffffffffu, d, off);
        float g = 1.f / (1.f + __expf(-d));
        float4 nv;
        nv.x = v.x + (oe.x - v.x) * g;
        nv.y = v.y + (oe.y - v.y) * g;
        nv.z = v.z + (oe.z - v.z) * g;
        nv.w = v.w + (oe.w - v.w) * g;
        ((float4*)ns)[warp * 32 + lane] = nv;
    }

    // 4) u1 = W @ sim_w[:H], u2 = W @ sim_w[H:]; 16 warps x 8 rows (gmem, L2-hot)
    {
        const float4 sw1 = ((const float4*)sim_w)[lane];
        const float4 sw2 = ((const float4*)sim_w)[32 + lane];
#pragma unroll
        for (int r = 0; r < 8; r += 2) {
            const int rowA2 = warp * 8 + r;
            float4 wa = ((const float4*)(attn_W + (size_t)rowA2 * H))[lane];
            float4 wb = ((const float4*)(attn_W + (size_t)(rowA2 + 1) * H))[lane];
            float a1 = wa.x*sw1.x + wa.y*sw1.y + wa.z*sw1.z + wa.w*sw1.w;
            float a2 = wa.x*sw2.x + wa.y*sw2.y + wa.z*sw2.z + wa.w*sw2.w;
            float b1 = wb.x*sw1.x + wb.y*sw1.y + wb.z*sw1.z + wb.w*sw1.w;
            float b2 = wb.x*sw2.x + wb.y*sw2.y + wb.z*sw2.z + wb.w*sw2.w;
#pragma unroll
            for (int off = 16; off > 0; off >>= 1) {
                a1 += __shfl_xor_sync(0xffffffffu, a1, off);
                a2 += __shfl_xor_sync(0xffffffffu, a2, off);
                b1 += __shfl_xor_sync(0xffffffffu, b1, off);
                b2 += __shfl_xor_sync(0xffffffffu, b2, off);
            }
            if (lane == 0) {
                u1s[rowA2]     = a1; u2s[rowA2]     = a2;
                u1s[rowA2 + 1] = b1; u2s[rowA2 + 1] = b2;
            }
        }
    }
    __syncthreads();   // ns, u1s, u2s ready (km already in registers)

    // ============ ATTEND: pure compute on register-resident km ============
    {
        const float4 u1v = ((const float4*)u1s)[lane];
        const float4 u2v = ((const float4*)u2s)[lane];
        const float  c   = sim_b[0];
        const float4* ns4 = (const float4*)ns;

        if (rA == orr) {
#pragma unroll
            for (int s = 0; s < S; s++) kmA[s] = ns4[s * 32 + lane];
        }
        if (rB == orr) {
#pragma unroll
            for (int s = 0; s < S; s++) kmB[s] = ns4[s * 32 + lane];
        }

        float aA = oA.x*u1v.x + oA.y*u1v.y + oA.z*u1v.z + oA.w*u1v.w;
        float aB = oB.x*u1v.x + oB.y*u1v.y + oB.z*u1v.z + oB.w*u1v.w;
        float pA[S], pB[S];
#pragma unroll
        for (int s = 0; s < S; s++) {
            pA[s] = kmA[s].x*u2v.x + kmA[s].y*u2v.y + kmA[s].z*u2v.z + kmA[s].w*u2v.w;
            pB[s] = kmB[s].x*u2v.x + kmB[s].y*u2v.y + kmB[s].z*u2v.z + kmB[s].w*u2v.w;
        }
#pragma unroll
        for (int off = 16; off > 0; off >>= 1) {
            aA += __shfl_xor_sync(0xffffffffu, aA, off);
            aB += __shfl_xor_sync(0xffffffffu, aB, off);
#pragma unroll
            for (int s = 0; s < S; s++) {
                pA[s] += __shfl_xor_sync(0xffffffffu, pA[s], off);
                pB[s] += __shfl_xor_sync(0xffffffffu, pB[s], off);
            }
        }

        float scA[S], scB[S];
        {
            float m = 0.f;
#pragma unroll
            for (int s = 0; s < S; s++) {
                float v = aA + pA[s] + c;
                scA[s] = v > 0.f ? v : 0.f;
                m = fmaxf(m, scA[s]);
            }
            float sum = 0.f;
#pragma unroll
            for (int s = 0; s < S; s++) { scA[s] = __expf(scA[s] - m); sum += scA[s]; }
            float inv = 1.f / sum;
#pragma unroll
            for (int s = 0; s < S; s++) scA[s] *= inv;
        }
        {
            float m = 0.f;
#pragma unroll
            for (int s = 0; s < S; s++) {
                float v = aB + pB[s] + c;
                scB[s] = v > 0.f ? v : 0.f;
                m = fmaxf(m, scB[s]);
            }
            float sum = 0.f;
#pragma unroll
            for (int s = 0; s < S; s++) { scB[s] = __expf(scB[s] - m); sum += scB[s]; }
            float inv = 1.f / sum;
#pragma unroll
            for (int s = 0; s < S; s++) scB[s] *= inv;
        }

        float4 cA = make_float4(0.f, 0.f, 0.f, 0.f);
        float4 cB = make_float4(0.f, 0.f, 0.f, 0.f);
#pragma unroll
        for (int s = 0; s < S; s++) {
            cA.x += scA[s] * kmA[s].x;  cA.y += scA[s] * kmA[s].y;
            cA.z += scA[s] * kmA[s].z;  cA.w += scA[s] * kmA[s].w;
            cB.x += scB[s] * kmB[s].x;  cB.y += scB[s] * kmB[s].y;
            cB.z += scB[s] * kmB[s].z;  cB.w += scB[s] * kmB[s].w;
        }
        ((float4*)(Cs + (warp * 2)     * H))[lane] = cA;
        ((float4*)(Cs + (warp * 2 + 1) * H))[lane] = cB;
    }
    __syncthreads();   // Cs complete

    // ============ GEMM: 16 warps, k-split halves ============
    // warp = kh*8 + rw : rows 4rw..4rw+3, cols 4*lane..+3, k in [kh*64, kh*64+64)
    const int kh   = warp >> 3;
    const int rw   = warp & 7;
    const int r0   = rw * 4;
    const int koff = kh * 64;
    const int row0 = blockIdx.x * 32;

    unsigned long long accL[4] = {0ull, 0ull, 0ull, 0ull};  // cols {c0,c1}
    unsigned long long accH[4] = {0ull, 0ull, 0ull, 0ull};  // cols {c2,c3}

#pragma unroll 4
    for (int kq = 0; kq < 16; kq++) {
        const int k = koff + kq * 4;
        float4 wv0 = ((const float4*)(Ws + (k + 0) * H))[lane];
        float4 wv1 = ((const float4*)(Ws + (k + 1) * H))[lane];
        float4 wv2 = ((const float4*)(Ws + (k + 2) * H))[lane];
        float4 wv3 = ((const float4*)(Ws + (k + 3) * H))[lane];
        unsigned long long w0L = pk2(wv0.x, wv0.y), w0H = pk2(wv0.z, wv0.w);
        unsigned long long w1L = pk2(wv1.x, wv1.y), w1H = pk2(wv1.z, wv1.w);
        unsigned long long w2L = pk2(wv2.x, wv2.y), w2H = pk2(wv2.z, wv2.w);
        unsigned long long w3L = pk2(wv3.x, wv3.y), w3H = pk2(wv3.z, wv3.w);
#pragma unroll
        for (int rr = 0; rr < 4; rr++) {
            float4 cv = *(const float4*)(Cs + (r0 + rr) * H + k);   // broadcast
            unsigned long long c0 = pk2(cv.x, cv.x);
            unsigned long long c1 = pk2(cv.y, cv.y);
            unsigned long long c2 = pk2(cv.z, cv.z);
            unsigned long long c3 = pk2(cv.w, cv.w);
            accL[rr] = fma2(c0, w0L, accL[rr]);
            accH[rr] = fma2(c0, w0H, accH[rr]);
            accL[rr] = fma2(c1, w1L, accL[rr]);
            accH[rr] = fma2(c1, w1H, accH[rr]);
            accL[rr] = fma2(c2, w2L, accL[rr]);
            accH[rr] = fma2(c2, w2H, accH[rr]);
            accL[rr] = fma2(c3, w3L, accL[rr]);
            accH[rr] = fma2(c3, w3H, accH[rr]);
        }
    }

    // k-half exchange: warps 8..15 publish partials, warps 0..7 combine+store.
    if (kh == 1) {
#pragma unroll
        for (int rr = 0; rr < 4; rr++) {
            redL[rr * 256 + rw * 32 + lane] = accL[rr];
            redH[rr * 256 + rw * 32 + lane] = accH[rr];
        }
    }
    __syncthreads();
    if (kh == 0) {
#pragma unroll
        for (int rr = 0; rr < 4; rr++) {
            unsigned long long oL = redL[rr * 256 + rw * 32 + lane];
            unsigned long long oH = redH[rr * 256 + rw * 32 + lane];
            unsigned long long tL = add2(accL[rr], oL);
            unsigned long long tH = add2(accH[rr], oH);
            float4 v;
            upk2(v.x, v.y, tL);
            upk2(v.z, v.w, tH);
            ((float4*)(out + (size_t)(row0 + r0 + rr) * H))[lane] = v;
        }
    }
}

// ---------------------------------------------------------------------------
extern "C" void kernel_launch(void* const* d_in, const int* in_sizes, int n_in,
                              void* d_out, int out_size)
{
    const float* memory   = (const float*)d_in[0];
    const float* o_emb_w  = (const float*)d_in[1];
    const float* o_emb_r  = (const float*)d_in[2];
    const float* attn_W   = (const float*)d_in[3];
    const float* sim_w    = (const float*)d_in[4];
    const float* sim_b    = (const float*)d_in[5];
    const float* forget_w = (const float*)d_in[6];
    const int*   o_rg     = (const int*)d_in[7];
    const int*   d_rg     = (const int*)d_in[8];
    float* out = (float*)d_out;

    cudaFuncSetAttribute(fused_kernel,
                         cudaFuncAttributeMaxDynamicSharedMemorySize, SMEM_BYTES);
    fused_kernel<<<NBLK, NT, SMEM_BYTES>>>(memory, o_emb_w, o_emb_r, attn_W,
                                           sim_w, sim_b, forget_w, o_rg, d_rg, out);
}

// round 7
// speedup vs baseline: 1.1167x; 1.1167x over previous
#include <cuda_runtime.h>
#include <math.h>

#define S    8
#define H    128
#define BB   4096
#define NBLK 128     // 32 batches (= 32 output rows) per block
#define NT   512

// Dynamic smem layout (floats)
#define OFF_WS   0            // Ws [128][128] 16384 floats; reused as reduction scratch
#define OFF_CS   16384        // Cs [32][128]   4096
#define OFF_NS   20480        // ns [8][128]    1024
#define OFF_U1   21504        // u1s[128]
#define OFF_U2   21632        // u2s[128]
#define SMEM_FLOATS 21760
#define SMEM_BYTES  (SMEM_FLOATS * 4)

// ---- packed f32x2 helpers (ptxas never auto-fuses; PTX only) ----
__device__ __forceinline__ unsigned long long pk2(float lo, float hi) {
    unsigned long long r;
    asm("mov.b64 %0, {%1, %2};" : "=l"(r) : "f"(lo), "f"(hi));
    return r;
}
__device__ __forceinline__ void upk2(float& lo, float& hi, unsigned long long v) {
    asm("mov.b64 {%0, %1}, %2;" : "=f"(lo), "=f"(hi) : "l"(v));
}
__device__ __forceinline__ unsigned long long fma2(unsigned long long a,
                                                   unsigned long long b,
                                                   unsigned long long c) {
    unsigned long long d;
    asm("fma.rn.f32x2 %0, %1, %2, %3;" : "=l"(d) : "l"(a), "l"(b), "l"(c));
    return d;
}

// One batch of attend: logits -> softmax -> ctx row into Cs.
__device__ __forceinline__ void attend_one(const float4* __restrict__ km,
                                           float4 o, float4 u1v, float4 u2v,
                                           float c, int lane,
                                           float* __restrict__ csRow)
{
    float a = o.x*u1v.x + o.y*u1v.y + o.z*u1v.z + o.w*u1v.w;
    float p[S];
#pragma unroll
    for (int s = 0; s < S; s++)
        p[s] = km[s].x*u2v.x + km[s].y*u2v.y + km[s].z*u2v.z + km[s].w*u2v.w;
#pragma unroll
    for (int off = 16; off > 0; off >>= 1) {
        a += __shfl_xor_sync(0xffffffffu, a, off);
#pragma unroll
        for (int s = 0; s < S; s++)
            p[s] += __shfl_xor_sync(0xffffffffu, p[s], off);
    }
    float m = 0.f;
#pragma unroll
    for (int s = 0; s < S; s++) {
        float v = a + p[s] + c;
        p[s] = v > 0.f ? v : 0.f;
        m = fmaxf(m, p[s]);
    }
    float sum = 0.f;
#pragma unroll
    for (int s = 0; s < S; s++) { p[s] = __expf(p[s] - m); sum += p[s]; }
    const float inv = 1.f / sum;
    float4 ctx = make_float4(0.f, 0.f, 0.f, 0.f);
#pragma unroll
    for (int s = 0; s < S; s++) {
        float sc = p[s] * inv;
        ctx.x += sc * km[s].x;
        ctx.y += sc * km[s].y;
        ctx.z += sc * km[s].z;
        ctx.w += sc * km[s].w;
    }
    ((float4*)csRow)[lane] = ctx;
}

__global__ __launch_bounds__(NT)
void fused_kernel(const float* __restrict__ memory,
                  const float* __restrict__ o_emb_w,
                  const float* __restrict__ o_emb_r,
                  const float* __restrict__ attn_W,
                  const float* __restrict__ sim_w,
                  const float* __restrict__ sim_b,
                  const float* __restrict__ forget_w,
                  const int*   __restrict__ o_rg_p,
                  const int*   __restrict__ d_rg,
                  float*       __restrict__ out)
{
    extern __shared__ float sm[];
    float* Ws  = sm + OFF_WS;
    float* Cs  = sm + OFF_CS;
    float* red = sm + OFF_WS;     // reduction scratch reuses Ws after GEMM reads
    float* ns  = sm + OFF_NS;
    float* u1s = sm + OFF_U1;
    float* u2s = sm + OFF_U2;

    const int tid  = threadIdx.x;
    const int warp = tid >> 5;       // 0..15
    const int lane = tid & 31;
    const int orr  = o_rg_p[0];

    // ============ PHASE A: issue all independent memory ops early ============
    // 1) attend gather (latency hidden under the rest of phase A)
    const int bA = blockIdx.x * 32 + warp * 2;
    const int bB = bA + 1;
    const int rA = d_rg[bA];
    const int rB = d_rg[bB];
    float4 kmA[S], kmB[S];
    {
        const float4* sA = (const float4*)(memory + (size_t)rA * (S * H));
        const float4* sB = (const float4*)(memory + (size_t)rB * (S * H));
#pragma unroll
        for (int s = 0; s < S; s++) kmA[s] = sA[s * 32 + lane];
#pragma unroll
        for (int s = 0; s < S; s++) kmB[s] = sB[s * 32 + lane];
    }
    float4 oA = ((const float4*)(o_emb_r + (size_t)bA * H))[lane];
    float4 oB = ((const float4*)(o_emb_r + (size_t)bB * H))[lane];

    // 2) W -> smem, full 128x128 (4096 float4, 8 per thread)
    {
        const float4* W4  = (const float4*)attn_W;
        float4*       Ws4 = (float4*)Ws;
#pragma unroll
        for (int i = 0; i < 8; i++) Ws4[tid + i * NT] = W4[tid + i * NT];
    }

    // 3) gate + new_slot (warps 0..7, warp w = slot w, warp-local)
    if (warp < 8) {
        const float4* sel4 = (const float4*)(memory + (size_t)orr * (S * H) + warp * H);
        float4 v  = sel4[lane];
        float4 oe = ((const float4*)o_emb_w)[lane];
        float4 f1 = ((const float4*)forget_w)[lane];
        float4 f2 = ((const float4*)(forget_w + H))[lane];
        float d = oe.x*f1.x + oe.y*f1.y + oe.z*f1.z + oe.w*f1.w
                + v.x*f2.x  + v.y*f2.y  + v.z*f2.z  + v.w*f2.w;
#pragma unroll
        for (int off = 16; off > 0; off >>= 1)
            d += __shfl_xor_sync(0xffffffffu, d, off);
        float g = 1.f / (1.f + __expf(-d));
        float4 nv;
        nv.x = v.x + (oe.x - v.x) * g;
        nv.y = v.y + (oe.y - v.y) * g;
        nv.z = v.z + (oe.z - v.z) * g;
        nv.w = v.w + (oe.w - v.w) * g;
        ((float4*)ns)[warp * 32 + lane] = nv;
    }

    // 4) u1 = W @ sim_w[:H], u2 = W @ sim_w[H:]; 16 warps x 8 rows (gmem, L2-hot)
    {
        const float4 sw1 = ((const float4*)sim_w)[lane];
        const float4 sw2 = ((const float4*)sim_w)[32 + lane];
#pragma unroll
        for (int r = 0; r < 8; r += 2) {
            const int rowA2 = warp * 8 + r;
            float4 wa = ((const float4*)(attn_W + (size_t)rowA2 * H))[lane];
            float4 wb = ((const float4*)(attn_W + (size_t)(rowA2 + 1) * H))[lane];
            float a1 = wa.x*sw1.x + wa.y*sw1.y + wa.z*sw1.z + wa.w*sw1.w;
            float a2 = wa.x*sw2.x + wa.y*sw2.y + wa.z*sw2.z + wa.w*sw2.w;
            float b1 = wb.x*sw1.x + wb.y*sw1.y + wb.z*sw1.z + wb.w*sw1.w;
            float b2 = wb.x*sw2.x + wb.y*sw2.y + wb.z*sw2.z + wb.w*sw2.w;
#pragma unroll
            for (int off = 16; off > 0; off >>= 1) {
                a1 += __shfl_xor_sync(0xffffffffu, a1, off);
                a2 += __shfl_xor_sync(0xffffffffu, a2, off);
                b1 += __shfl_xor_sync(0xffffffffu, b1, off);
                b2 += __shfl_xor_sync(0xffffffffu, b2, off);
            }
            if (lane == 0) {
                u1s[rowA2]     = a1; u2s[rowA2]     = a2;
                u1s[rowA2 + 1] = b1; u2s[rowA2 + 1] = b2;
            }
        }
    }
    __syncthreads();   // ns, u1s, u2s ready (km already in registers)

    // ============ ATTEND: sequential per batch (caps live registers) ============
    {
        const float4 u1v = ((const float4*)u1s)[lane];
        const float4 u2v = ((const float4*)u2s)[lane];
        const float  c   = sim_b[0];
        const float4* ns4 = (const float4*)ns;

        if (rA == orr) {
#pragma unroll
            for (int s = 0; s < S; s++) kmA[s] = ns4[s * 32 + lane];
        }
        if (rB == orr) {
#pragma unroll
            for (int s = 0; s < S; s++) kmB[s] = ns4[s * 32 + lane];
        }

        attend_one(kmA, oA, u1v, u2v, c, lane, Cs + (warp * 2)     * H);
        attend_one(kmB, oB, u1v, u2v, c, lane, Cs + (warp * 2 + 1) * H);
    }
    __syncthreads();   // Cs complete

    // ============ GEMM: 16 warps = 4 row-groups x 4 k-quarters ============
    // warp: rg = warp & 3 (rows rg*8..+8), kh = warp >> 2 (k in [kh*32, kh*32+32))
    // thread: cols lane*4..lane*4+3, 8x4 microtile.
    const int rg   = warp & 3;
    const int kh   = warp >> 2;
    const int rows0 = rg * 8;
    const int koff  = kh * 32;
    const int row0  = blockIdx.x * 32;

    unsigned long long accL[8], accH[8];
#pragma unroll
    for (int rr = 0; rr < 8; rr++) { accL[rr] = 0ull; accH[rr] = 0ull; }

#pragma unroll 2
    for (int kq = 0; kq < 8; kq++) {
        const int k = koff + kq * 4;
        float4 wv0 = ((const float4*)(Ws + (k + 0) * H))[lane];
        float4 wv1 = ((const float4*)(Ws + (k + 1) * H))[lane];
        float4 wv2 = ((const float4*)(Ws + (k + 2) * H))[lane];
        float4 wv3 = ((const float4*)(Ws + (k + 3) * H))[lane];
        unsigned long long w0L = pk2(wv0.x, wv0.y), w0H = pk2(wv0.z, wv0.w);
        unsigned long long w1L = pk2(wv1.x, wv1.y), w1H = pk2(wv1.z, wv1.w);
        unsigned long long w2L = pk2(wv2.x, wv2.y), w2H = pk2(wv2.z, wv2.w);
        unsigned long long w3L = pk2(wv3.x, wv3.y), w3H = pk2(wv3.z, wv3.w);
#pragma unroll
        for (int rr = 0; rr < 8; rr++) {
            float4 cv = *(const float4*)(Cs + (rows0 + rr) * H + k);   // broadcast
            unsigned long long c0 = pk2(cv.x, cv.x);
            unsigned long long c1 = pk2(cv.y, cv.y);
            unsigned long long c2 = pk2(cv.z, cv.z);
            unsigned long long c3 = pk2(cv.w, cv.w);
            accL[rr] = fma2(c0, w0L, accL[rr]);
            accH[rr] = fma2(c0, w0H, accH[rr]);
            accL[rr] = fma2(c1, w1L, accL[rr]);
            accH[rr] = fma2(c1, w1H, accH[rr]);
            accL[rr] = fma2(c2, w2L, accL[rr]);
            accH[rr] = fma2(c2, w2H, accH[rr]);
            accL[rr] = fma2(c3, w3L, accL[rr]);
            accH[rr] = fma2(c3, w3H, accH[rr]);
        }
    }

    __syncthreads();   // all Ws reads done; safe to reuse as reduction scratch

    // k-quarter reduction: kh=1..3 publish partials (48KB into old Ws region),
    // kh=0 combines and stores.
    if (kh != 0) {
#pragma unroll
        for (int rr = 0; rr < 8; rr++) {
            float4 v;
            upk2(v.x, v.y, accL[rr]);
            upk2(v.z, v.w, accH[rr]);
            ((float4*)(red + ((kh - 1) * 32 + rows0 + rr) * H))[lane] = v;
        }
    }
    __syncthreads();
    if (kh == 0) {
#pragma unroll
        for (int rr = 0; rr < 8; rr++) {
            float4 v;
            upk2(v.x, v.y, accL[rr]);
            upk2(v.z, v.w, accH[rr]);
#pragma unroll
            for (int q = 0; q < 3; q++) {
                float4 r = ((const float4*)(red + (q * 32 + rows0 + rr) * H))[lane];
                v.x += r.x; v.y += r.y; v.z += r.z; v.w += r.w;
            }
            ((float4*)(out + (size_t)(row0 + rows0 + rr) * H))[lane] = v;
        }
    }
}

// ---------------------------------------------------------------------------
extern "C" void kernel_launch(void* const* d_in, const int* in_sizes, int n_in,
                              void* d_out, int out_size)
{
    const float* memory   = (const float*)d_in[0];
    const float* o_emb_w  = (const float*)d_in[1];
    const float* o_emb_r  = (const float*)d_in[2];
    const float* attn_W   = (const float*)d_in[3];
    const float* sim_w    = (const float*)d_in[4];
    const float* sim_b    = (const float*)d_in[5];
    const float* forget_w = (const float*)d_in[6];
    const int*   o_rg     = (const int*)d_in[7];
    const int*   d_rg     = (const int*)d_in[8];
    float* out = (float*)d_out;

    cudaFuncSetAttribute(fused_kernel,
                         cudaFuncAttributeMaxDynamicSharedMemorySize, SMEM_BYTES);
    fused_kernel<<<NBLK, NT, SMEM_BYTES>>>(memory, o_emb_w, o_emb_r, attn_W,
                                           sim_w, sim_b, forget_w, o_rg, d_rg, out);
}

// round 8
// speedup vs baseline: 1.1754x; 1.0526x over previous
#include <cuda_runtime.h>
#include <math.h>
#include <stdint.h>

#define S    8
#define H    128
#define BB   4096
#define NBLK 128     // 32 batches (= 32 output rows) per block
#define NT   512

// Dynamic smem layout (floats)
#define OFF_WS   0            // Ws [128][128] 16384 floats; reused as reduction scratch
#define OFF_CS   16384        // Cs [32][128]   4096
#define OFF_NS   20480        // ns [8][128]    1024
#define OFF_U1   21504        // u1s[128]
#define OFF_U2   21632        // u2s[128]
#define SMEM_FLOATS 21760
#define SMEM_BYTES  (SMEM_FLOATS * 4)

// ---- packed f32x2 helpers (ptxas never auto-fuses; PTX only) ----
__device__ __forceinline__ unsigned long long pk2(float lo, float hi) {
    unsigned long long r;
    asm("mov.b64 %0, {%1, %2};" : "=l"(r) : "f"(lo), "f"(hi));
    return r;
}
__device__ __forceinline__ void upk2(float& lo, float& hi, unsigned long long v) {
    asm("mov.b64 {%0, %1}, %2;" : "=f"(lo), "=f"(hi) : "l"(v));
}
__device__ __forceinline__ unsigned long long fma2(unsigned long long a,
                                                   unsigned long long b,
                                                   unsigned long long c) {
    unsigned long long d;
    asm("fma.rn.f32x2 %0, %1, %2, %3;" : "=l"(d) : "l"(a), "l"(b), "l"(c));
    return d;
}
__device__ __forceinline__ void cp_async16(uint32_t saddr, const void* gptr) {
    asm volatile("cp.async.cg.shared.global [%0], [%1], 16;"
                 :: "r"(saddr), "l"(gptr));
}

// Attend one batch via fold-reduction: 23 SHFL, 1 expf per lane.
__device__ __forceinline__ void attend_fold(const float4* __restrict__ km,
                                            float4 o, float4 u1v, float4 u2v,
                                            float c, int lane,
                                            float* __restrict__ csRow)
{
    const unsigned F = 0xffffffffu;
    // per-lane partials; fold 'a' into every p so one reduction suffices
    float a = o.x*u1v.x + o.y*u1v.y + o.z*u1v.z + o.w*u1v.w;
    float p[S];
#pragma unroll
    for (int s = 0; s < S; s++)
        p[s] = km[s].x*u2v.x + km[s].y*u2v.y + km[s].z*u2v.z + km[s].w*u2v.w + a;

    // fold 16: keep 4 values, send 4
    const bool h16 = lane & 16;
    float k0 = h16 ? p[4] : p[0], k1 = h16 ? p[5] : p[1];
    float k2 = h16 ? p[6] : p[2], k3 = h16 ? p[7] : p[3];
    float s0 = h16 ? p[0] : p[4], s1 = h16 ? p[1] : p[5];
    float s2 = h16 ? p[2] : p[6], s3 = h16 ? p[3] : p[7];
    k0 += __shfl_xor_sync(F, s0, 16);
    k1 += __shfl_xor_sync(F, s1, 16);
    k2 += __shfl_xor_sync(F, s2, 16);
    k3 += __shfl_xor_sync(F, s3, 16);
    // fold 8: keep 2, send 2
    const bool h8 = lane & 8;
    float m0 = h8 ? k2 : k0, m1 = h8 ? k3 : k1;
    float t0 = h8 ? k0 : k2, t1 = h8 ? k1 : k3;
    m0 += __shfl_xor_sync(F, t0, 8);
    m1 += __shfl_xor_sync(F, t1, 8);
    // fold 4: keep 1, send 1
    const bool h4 = lane & 4;
    float q = h4 ? m1 : m0;
    float u = h4 ? m0 : m1;
    q += __shfl_xor_sync(F, u, 4);
    // butterfly over remaining lane bits 0,1
    q += __shfl_xor_sync(F, q, 2);
    q += __shfl_xor_sync(F, q, 1);
    // lane class (lane>>2)&7 now holds logit for slot=class

    float L = q + c;
    L = L > 0.f ? L : 0.f;
    // max & sum across the 8 classes (bits 2,3,4)
    float mx = L;
    mx = fmaxf(mx, __shfl_xor_sync(F, mx, 4));
    mx = fmaxf(mx, __shfl_xor_sync(F, mx, 8));
    mx = fmaxf(mx, __shfl_xor_sync(F, mx, 16));
    float e = __expf(L - mx);
    float sum = e;
    sum += __shfl_xor_sync(F, sum, 4);
    sum += __shfl_xor_sync(F, sum, 8);
    sum += __shfl_xor_sync(F, sum, 16);
    float mysc = e / sum;

    float4 ctx = make_float4(0.f, 0.f, 0.f, 0.f);
#pragma unroll
    for (int s = 0; s < S; s++) {
        float sc = __shfl_sync(F, mysc, s << 2);   // lane s*4 has class s
        ctx.x += sc * km[s].x;
        ctx.y += sc * km[s].y;
        ctx.z += sc * km[s].z;
        ctx.w += sc * km[s].w;
    }
    ((float4*)csRow)[lane] = ctx;
}

__global__ __launch_bounds__(NT)
void fused_kernel(const float* __restrict__ memory,
                  const float* __restrict__ o_emb_w,
                  const float* __restrict__ o_emb_r,
                  const float* __restrict__ attn_W,
                  const float* __restrict__ sim_w,
                  const float* __restrict__ sim_b,
                  const float* __restrict__ forget_w,
                  const int*   __restrict__ o_rg_p,
                  const int*   __restrict__ d_rg,
                  float*       __restrict__ out)
{
    extern __shared__ float sm[];
    float* Ws  = sm + OFF_WS;
    float* Cs  = sm + OFF_CS;
    float* red = sm + OFF_WS;     // reduction scratch reuses Ws after GEMM reads
    float* ns  = sm + OFF_NS;
    float* u1s = sm + OFF_U1;
    float* u2s = sm + OFF_U2;

    const int tid  = threadIdx.x;
    const int warp = tid >> 5;       // 0..15
    const int lane = tid & 31;
    const int orr  = o_rg_p[0];
    const unsigned F = 0xffffffffu;

    // ============ PHASE A ============
    // 1) W -> Ws via cp.async (no register staging)
    {
        uint32_t ws_addr = (uint32_t)__cvta_generic_to_shared(Ws);
        const float4* W4 = (const float4*)attn_W;
#pragma unroll
        for (int i = 0; i < 8; i++)
            cp_async16(ws_addr + (uint32_t)(tid + i * NT) * 16u, W4 + tid + i * NT);
        asm volatile("cp.async.commit_group;");
    }

    // 2) gather A (+ o_emb_r rows) early — latency hides under prep
    const int bA = blockIdx.x * 32 + warp * 2;
    const int bB = bA + 1;
    const int rA = d_rg[bA];
    const int rB = d_rg[bB];
    float4 kmA[S];
    {
        const float4* sA = (const float4*)(memory + (size_t)rA * (S * H));
#pragma unroll
        for (int s = 0; s < S; s++) kmA[s] = sA[s * 32 + lane];
    }
    float4 oA = ((const float4*)(o_emb_r + (size_t)bA * H))[lane];
    float4 oB = ((const float4*)(o_emb_r + (size_t)bB * H))[lane];

    // 3) gate + new_slot (warps 0..7; warp w = slot w)
    if (warp < 8) {
        const float4* sel4 = (const float4*)(memory + (size_t)orr * (S * H) + warp * H);
        float4 v  = sel4[lane];
        float4 oe = ((const float4*)o_emb_w)[lane];
        float4 f1 = ((const float4*)forget_w)[lane];
        float4 f2 = ((const float4*)(forget_w + H))[lane];
        float d = oe.x*f1.x + oe.y*f1.y + oe.z*f1.z + oe.w*f1.w
                + v.x*f2.x  + v.y*f2.y  + v.z*f2.z  + v.w*f2.w;
#pragma unroll
        for (int off = 16; off > 0; off >>= 1)
            d += __shfl_xor_sync(F, d, off);
        float g = 1.f / (1.f + __expf(-d));
        float4 nv;
        nv.x = v.x + (oe.x - v.x) * g;
        nv.y = v.y + (oe.y - v.y) * g;
        nv.z = v.z + (oe.z - v.z) * g;
        nv.w = v.w + (oe.w - v.w) * g;
        ((float4*)ns)[warp * 32 + lane] = nv;
    }

    asm volatile("cp.async.wait_group 0;" ::: "memory");
    __syncthreads();   // Ws + ns visible

    // 4) gather B now (hides under u1/u2 + attendA)
    float4 kmB[S];
    {
        const float4* sB = (const float4*)(memory + (size_t)rB * (S * H));
#pragma unroll
        for (int s = 0; s < S; s++) kmB[s] = sB[s * 32 + lane];
    }

    // 5) u1 = W @ sim_w[:H], u2 = W @ sim_w[H:] — from smem Ws (single W L2 read)
    {
        const float4 sw1 = ((const float4*)sim_w)[lane];
        const float4 sw2 = ((const float4*)sim_w)[32 + lane];
#pragma unroll
        for (int it = 0; it < 4; it++) {
            const int rowA2 = warp * 8 + it * 2;
            float4 wa = ((const float4*)(Ws + rowA2 * H))[lane];
            float4 wb = ((const float4*)(Ws + (rowA2 + 1) * H))[lane];
            float v0 = wa.x*sw1.x + wa.y*sw1.y + wa.z*sw1.z + wa.w*sw1.w;  // u1[rowA]
            float v1 = wa.x*sw2.x + wa.y*sw2.y + wa.z*sw2.z + wa.w*sw2.w;  // u2[rowA]
            float v2 = wb.x*sw1.x + wb.y*sw1.y + wb.z*sw1.z + wb.w*sw1.w;  // u1[rowB]
            float v3 = wb.x*sw2.x + wb.y*sw2.y + wb.z*sw2.z + wb.w*sw2.w;  // u2[rowB]
            const bool h16 = lane & 16;
            float k0 = h16 ? v2 : v0, k1 = h16 ? v3 : v1;
            float s0 = h16 ? v0 : v2, s1 = h16 ? v1 : v3;
            k0 += __shfl_xor_sync(F, s0, 16);
            k1 += __shfl_xor_sync(F, s1, 16);
            const bool h8 = lane & 8;
            float m = h8 ? k1 : k0;
            float t = h8 ? k0 : k1;
            m += __shfl_xor_sync(F, t, 8);
            m += __shfl_xor_sync(F, m, 4);
            m += __shfl_xor_sync(F, m, 2);
            m += __shfl_xor_sync(F, m, 1);
            if ((lane & 7) == 0) {
                const int cls = lane >> 3;   // 0:u1[rA] 1:u2[rA] 2:u1[rB] 3:u2[rB]
                float* dst = (cls & 1) ? u2s : u1s;
                dst[rowA2 + ((cls & 2) >> 1)] = m;
            }
        }
    }
    __syncthreads();   // u1s/u2s ready

    // ============ ATTEND ============
    {
        const float4 u1v = ((const float4*)u1s)[lane];
        const float4 u2v = ((const float4*)u2s)[lane];
        const float  c   = sim_b[0];
        const float4* ns4 = (const float4*)ns;
        if (rA == orr) {
#pragma unroll
            for (int s = 0; s < S; s++) kmA[s] = ns4[s * 32 + lane];
        }
        if (rB == orr) {
#pragma unroll
            for (int s = 0; s < S; s++) kmB[s] = ns4[s * 32 + lane];
        }
        attend_fold(kmA, oA, u1v, u2v, c, lane, Cs + (warp * 2)     * H);
        attend_fold(kmB, oB, u1v, u2v, c, lane, Cs + (warp * 2 + 1) * H);
    }
    __syncthreads();   // Cs complete

    // ============ GEMM: 16 warps = 4 row-groups x 4 k-quarters ============
    const int rg    = warp & 3;
    const int kh    = warp >> 2;
    const int rows0 = rg * 8;
    const int koff  = kh * 32;
    const int row0  = blockIdx.x * 32;

    unsigned long long accL[8], accH[8];
#pragma unroll
    for (int rr = 0; rr < 8; rr++) { accL[rr] = 0ull; accH[rr] = 0ull; }

#pragma unroll 2
    for (int kq = 0; kq < 8; kq++) {
        const int k = koff + kq * 4;
        float4 wv0 = ((const float4*)(Ws + (k + 0) * H))[lane];
        float4 wv1 = ((const float4*)(Ws + (k + 1) * H))[lane];
        float4 wv2 = ((const float4*)(Ws + (k + 2) * H))[lane];
        float4 wv3 = ((const float4*)(Ws + (k + 3) * H))[lane];
        unsigned long long w0L = pk2(wv0.x, wv0.y), w0H = pk2(wv0.z, wv0.w);
        unsigned long long w1L = pk2(wv1.x, wv1.y), w1H = pk2(wv1.z, wv1.w);
        unsigned long long w2L = pk2(wv2.x, wv2.y), w2H = pk2(wv2.z, wv2.w);
        unsigned long long w3L = pk2(wv3.x, wv3.y), w3H = pk2(wv3.z, wv3.w);
#pragma unroll
        for (int rr = 0; rr < 8; rr++) {
            float4 cv = *(const float4*)(Cs + (rows0 + rr) * H + k);   // broadcast
            unsigned long long c0 = pk2(cv.x, cv.x);
            unsigned long long c1 = pk2(cv.y, cv.y);
            unsigned long long c2 = pk2(cv.z, cv.z);
            unsigned long long c3 = pk2(cv.w, cv.w);
            accL[rr] = fma2(c0, w0L, accL[rr]);
            accH[rr] = fma2(c0, w0H, accH[rr]);
            accL[rr] = fma2(c1, w1L, accL[rr]);
            accH[rr] = fma2(c1, w1H, accH[rr]);
            accL[rr] = fma2(c2, w2L, accL[rr]);
            accH[rr] = fma2(c2, w2H, accH[rr]);
            accL[rr] = fma2(c3, w3L, accL[rr]);
            accH[rr] = fma2(c3, w3H, accH[rr]);
        }
    }

    __syncthreads();   // all Ws reads done; safe to reuse as reduction scratch

    if (kh != 0) {
#pragma unroll
        for (int rr = 0; rr < 8; rr++) {
            float4 v;
            upk2(v.x, v.y, accL[rr]);
            upk2(v.z, v.w, accH[rr]);
            ((float4*)(red + ((kh - 1) * 32 + rows0 + rr) * H))[lane] = v;
        }
    }
    __syncthreads();
    if (kh == 0) {
#pragma unroll
        for (int rr = 0; rr < 8; rr++) {
            float4 v;
            upk2(v.x, v.y, accL[rr]);
            upk2(v.z, v.w, accH[rr]);
#pragma unroll
            for (int q = 0; q < 3; q++) {
                float4 r = ((const float4*)(red + (q * 32 + rows0 + rr) * H))[lane];
                v.x += r.x; v.y += r.y; v.z += r.z; v.w += r.w;
            }
            ((float4*)(out + (size_t)(row0 + rows0 + rr) * H))[lane] = v;
        }
    }
}

// ---------------------------------------------------------------------------
extern "C" void kernel_launch(void* const* d_in, const int* in_sizes, int n_in,
                              void* d_out, int out_size)
{
    const float* memory   = (const float*)d_in[0];
    const float* o_emb_w  = (const float*)d_in[1];
    const float* o_emb_r  = (const float*)d_in[2];
    const float* attn_W   = (const float*)d_in[3];
    const float* sim_w    = (const float*)d_in[4];
    const float* sim_b    = (const float*)d_in[5];
    const float* forget_w = (const float*)d_in[6];
    const int*   o_rg     = (const int*)d_in[7];
    const int*   d_rg     = (const int*)d_in[8];
    float* out = (float*)d_out;

    cudaFuncSetAttribute(fused_kernel,
                         cudaFuncAttributeMaxDynamicSharedMemorySize, SMEM_BYTES);
    fused_kernel<<<NBLK, NT, SMEM_BYTES>>>(memory, o_emb_w, o_emb_r, attn_W,
                                           sim_w, sim_b, forget_w, o_rg, d_rg, out);
}